// round 10
// baseline (speedup 1.0000x reference)
#include <cuda_runtime.h>

#define NN 1395
#define EE 44640
#define G1 175          // ceil(EE/256): edge-grain grid
#define G2 512          // fc kernel grid
#define G3 384          // conv kernel grid (== conv2 item count)
#define GB 592          // kB grid

// ---------------- scratch (device globals) ----------------------------------
__device__ __align__(16) float g_xw[NN * 3];
__device__ __align__(16) float g_acc[NN * 3 + 1];
__device__ int   g_deg[NN];
__device__ float g_dinv[NN];
__device__ unsigned g_pk[EE];
__device__ __align__(16) float g_v1[2048];
__device__ __align__(16) float g_v2[4096];
__device__ __align__(16) float g_c1[32 * 58 * 58];
__device__ __align__(16) float g_c2[32 * 54 * 54];
__device__ __align__(16) float g_c3[64 * 52 * 52];
__device__ __align__(16) float g_c4[64 * 50 * 50];
__device__ __align__(16) float g_f3[2048];
__device__ __align__(16) float g_f4[2048];

// ---------------- software grid barrier (generation-based) ------------------
__device__ unsigned g_cnt = 0;
__device__ volatile unsigned g_rel = 0;

__device__ __forceinline__ void gsync(unsigned nb) {
    __syncthreads();
    if (threadIdx.x == 0) {
        __threadfence();
        unsigned gen = g_rel;
        if (atomicAdd(&g_cnt, 1u) == nb - 1u) {
            g_cnt = 0u;
            __threadfence();
            g_rel = gen + 1u;
        } else {
            while (g_rel == gen) __nanosleep(64);
        }
    }
    __syncthreads();
}

__device__ __forceinline__ float warp_red(float a) {
#pragma unroll
    for (int o = 16; o > 0; o >>= 1)
        a += __shfl_down_sync(0xFFFFFFFFu, a, o);
    return a;
}

// ---------------- kernel 1: whole GCN (edge-grain persistent) ----------------
extern "C" __global__ void __launch_bounds__(256, 4) k_gcn(
    const float* __restrict__ x, const void* __restrict__ ei,
    const float* __restrict__ W1, const float* __restrict__ b1,
    const float* __restrict__ W2,
    const float* __restrict__ fc1_b, const float* __restrict__ fc3_b) {
    const int T = G1 * 256;
    const int gt = blockIdx.x * 256 + threadIdx.x;

    // s0: seed g_f3 (fc3 bias) + g_v1 (fc1 bias); detect dtype; pack + degree
    for (int i = gt; i < 2048; i += T) {
        g_f3[i] = fc3_b[i];
        g_v1[i] = fc1_b[i];
    }
    {
        int e = gt;
        const unsigned* u = (const unsigned*)ei;
        unsigned odd = (e < EE) ? u[2 * e + 1] : 0u;
        int any = __syncthreads_or(odd != 0u);   // per-block slice: int64 <=> all zero
        int idx64 = !any;
        if (e < EE) {
            int s, d;
            if (idx64) {
                s = (int)((const long long*)ei)[e];
                d = (int)((const long long*)ei)[EE + e];
            } else {
                s = ((const int*)ei)[e];
                d = ((const int*)ei)[EE + e];
            }
            unsigned pk = 0xFFFFFFFFu;
            if (s >= 0 && s < NN && d >= 0 && d < NN) {
                pk = (unsigned)s | ((unsigned)d << 11);
                atomicAdd(&g_deg[d], 1);
            }
            g_pk[e] = pk;
        }
    }
    gsync(G1);

    // s1: node1 = dinv + xw1 + self term (x[:, :3] zeroed => cols 3..5 only)
    if (gt < NN) {
        int i = gt;
        float di = rsqrtf((float)(g_deg[i] + 1));
        g_deg[i] = 0;                 // self-clear for next graph replay
        g_dinv[i] = di;
        float x3 = x[i * 6 + 3], x4 = x[i * 6 + 4], x5 = x[i * 6 + 5];
        float d2 = di * di;
#pragma unroll
        for (int c = 0; c < 3; c++) {
            float xw = x3 * W1[9 + c] + x4 * W1[12 + c] + x5 * W1[15 + c];
            g_xw[i * 3 + c] = xw;
            g_acc[i * 3 + c] = d2 * xw;
        }
    }
    gsync(G1);

    // s2: scatter layer 1
    if (gt < EE) {
        unsigned pk = g_pk[gt];
        if (pk != 0xFFFFFFFFu) {
            int s = pk & 2047, d = pk >> 11;
            float n = g_dinv[s] * g_dinv[d];
            atomicAdd(&g_acc[d * 3 + 0], n * g_xw[s * 3 + 0]);
            atomicAdd(&g_acc[d * 3 + 1], n * g_xw[s * 3 + 1]);
            atomicAdd(&g_acc[d * 3 + 2], n * g_xw[s * 3 + 2]);
        }
    }
    gsync(G1);

    // s3: node2 = leaky(acc+b1) -> xw2 + self term  (acc via L2: atomics wrote it)
    if (gt < NN) {
        int i = gt;
        float h[3];
#pragma unroll
        for (int c = 0; c < 3; c++) {
            float v = __ldcg(&g_acc[i * 3 + c]) + b1[c];
            h[c] = (v >= 0.f) ? v : 0.2f * v;
        }
        float di = g_dinv[i];
        float d2 = di * di;
#pragma unroll
        for (int c = 0; c < 3; c++) {
            float xw = h[0] * W2[c] + h[1] * W2[3 + c] + h[2] * W2[6 + c];
            g_xw[i * 3 + c] = xw;
            g_acc[i * 3 + c] = d2 * xw;
        }
    }
    gsync(G1);

    // s4: scatter layer 2 (g_xw was read in s2 then rewritten in s3 -> __ldcg)
    if (gt < EE) {
        unsigned pk = g_pk[gt];
        if (pk != 0xFFFFFFFFu) {
            int s = pk & 2047, d = pk >> 11;
            float n = g_dinv[s] * g_dinv[d];
            atomicAdd(&g_acc[d * 3 + 0], n * __ldcg(&g_xw[s * 3 + 0]));
            atomicAdd(&g_acc[d * 3 + 1], n * __ldcg(&g_xw[s * 3 + 1]));
            atomicAdd(&g_acc[d * 3 + 2], n * __ldcg(&g_xw[s * 3 + 2]));
        }
    }
    // leaky(acc + b2) is fused into k_fc's x-load (cross-launch: L1 flushed)
}

// ---------------- kernel 2: fc1 + fc2 (+ conv bias seeding) ------------------
extern "C" __global__ void __launch_bounds__(256, 4) k_fc(
    const float* __restrict__ b2,
    const float* __restrict__ fc1_w,
    const float* __restrict__ fc2_w, const float* __restrict__ fc2_b,
    const float* __restrict__ c2_b, const float* __restrict__ c3_b,
    const float* __restrict__ c4_b) {
    __shared__ __align__(16) float xs[4185];
    const int T = G2 * 256;
    const int gt = blockIdx.x * 256 + threadIdx.x;

    // stage A: seed conv accumulators; fc1 with fused leaky(acc + b2)
    for (int i = gt; i < 32 * 54 * 54; i += T) g_c2[i] = c2_b[i / (54 * 54)];
    for (int i = gt; i < 64 * 52 * 52; i += T) g_c3[i] = c3_b[i / (52 * 52)];
    for (int i = gt; i < 64 * 50 * 50; i += T) g_c4[i] = c4_b[i / (50 * 50)];
    {
        float bb0 = b2[0], bb1 = b2[1], bb2 = b2[2];
        for (int i = threadIdx.x; i < 4185; i += 256) {
            int c = i % 3;
            float bias = (c == 0) ? bb0 : (c == 1 ? bb1 : bb2);
            float v = g_acc[i] + bias;
            xs[i] = (v >= 0.f) ? v : 0.2f * v;
        }
        __syncthreads();
        // 4096 warps over 2048 rows: 2 warps per row, half-columns each,
        // atomicAdd into fc1_b-seeded g_v1.
        int warp = gt >> 5, lane = gt & 31;
        int row = warp & 2047;
        int half = warp >> 11;
        int start = half ? 2093 : 0;
        int end = half ? 4185 : 2093;
        const float* wr = fc1_w + (size_t)row * 4185;
        float a = 0.f;
#pragma unroll 4
        for (int i = start + lane; i < end; i += 32) a += __ldcs(&wr[i]) * xs[i];
        a = warp_red(a);
        if (lane == 0) atomicAdd(&g_v1[row], a);
    }
    gsync(G2);

    // stage B: fc2 [4096 x 2048], warp per row (g_v1 first-touched here: plain ok)
    {
        for (int i = threadIdx.x; i < 2048; i += 256) xs[i] = g_v1[i];
        __syncthreads();
        int warp = gt >> 5, lane = gt & 31;
        const float4* w4 = (const float4*)(fc2_w + (size_t)warp * 2048);
        const float4* xs4 = (const float4*)xs;
        float a = 0.f;
#pragma unroll 4
        for (int i = lane; i < 512; i += 32) {
            float4 w = __ldcs(&w4[i]);
            float4 xv = xs4[i];
            a += w.x * xv.x + w.y * xv.y + w.z * xv.z + w.w * xv.w;
        }
        a = warp_red(a);
        if (lane == 0) g_v2[warp] = a + fc2_b[warp];
    }
}

// ---------------- conv stage (guarded; block-uniform branches) ---------------
template <int CO, int CI, int KH, int KW, int OCB, int SPLIT>
__device__ __forceinline__ void conv_stage(const float* __restrict__ in,
                                           const float* __restrict__ w,
                                           const float* __restrict__ bia,
                                           float* __restrict__ out,
                                           int H, int W, int OH, int OW,
                                           float* sw) {
    const int CIP = CI / SPLIT;
    const int NTILE = (OH * OW + 255) / 256;
    const int ITEMS = (CO / OCB) * SPLIT * NTILE;
    int it = blockIdx.x;
    if (it >= ITEMS) return;   // block-uniform; returning blocks rejoin at gsync (caller)
    int tile = it % NTILE;
    int grp = it / NTILE;
    int ocg = grp / SPLIT;
    int part = grp - ocg * SPLIT;
    int oc0 = ocg * OCB;
    int ic0 = part * CIP;
    for (int i = threadIdx.x; i < OCB * CIP * KH * KW; i += 256) {
        int o = i / (CIP * KH * KW);
        int rem = i - o * (CIP * KH * KW);
        int ic = rem / (KH * KW);
        int k = rem - ic * (KH * KW);
        sw[i] = w[((size_t)(oc0 + o) * CI + ic0 + ic) * (KH * KW) + k];
    }
    __syncthreads();
    int p = tile * 256 + threadIdx.x;
    if (p < OH * OW) {
        int oy = p / OW, ox = p - oy * OW;
        float acc[OCB];
#pragma unroll
        for (int o = 0; o < OCB; o++) acc[o] = (SPLIT == 1) ? bia[oc0 + o] : 0.f;
        for (int ic = 0; ic < CIP; ic++) {
            const float* ip = in + ((size_t)(ic0 + ic) * H + oy) * W + ox;
            const float* wp = sw + ic * KH * KW;
#pragma unroll
            for (int i = 0; i < KH; i++)
#pragma unroll
                for (int j = 0; j < KW; j++) {
                    float v = ip[i * W + j];
#pragma unroll
                    for (int o = 0; o < OCB; o++)
                        acc[o] += wp[o * CIP * KH * KW + i * KW + j] * v;
                }
        }
#pragma unroll
        for (int o = 0; o < OCB; o++) {
            size_t oi = ((size_t)(oc0 + o) * OH + oy) * OW + ox;
            if (SPLIT == 1) out[oi] = acc[o];
            else atomicAdd(&out[oi], acc[o]);
        }
    }
    __syncthreads();
}

// ---------------- kernel 3: conv chain ---------------------------------------
extern "C" __global__ void __launch_bounds__(256, 4) k_conv(
    const float* __restrict__ c1_w, const float* __restrict__ c1_b,
    const float* __restrict__ c2_w, const float* __restrict__ c2_b,
    const float* __restrict__ c3_w, const float* __restrict__ c3_b,
    const float* __restrict__ c4_w, const float* __restrict__ c4_b) {
    __shared__ __align__(16) float sw[1152];
    // each inter-stage buffer is written-once-then-read within this kernel,
    // with no earlier in-kernel reads -> plain (L1) loads are stale-free.
    conv_stage<32, 1, 7, 7, 4, 1>(g_v2, c1_w, c1_b, g_c1, 64, 64, 58, 58, sw);
    gsync(G3);
    conv_stage<32, 32, 5, 5, 4, 4>(g_c1, c2_w, c2_b, g_c2, 58, 58, 54, 54, sw);
    gsync(G3);
    conv_stage<64, 32, 3, 3, 8, 2>(g_c2, c3_w, c3_b, g_c3, 54, 54, 52, 52, sw);
    gsync(G3);
    conv_stage<64, 64, 3, 3, 8, 4>(g_c3, c4_w, c4_b, g_c4, 52, 52, 50, 50, sw);
}

// ---------------- kernel 4: fc3 (8-row groups) + fc4 + fc5 (proven) ----------
extern "C" __global__ void __launch_bounds__(256, 4) kB(
    const float* __restrict__ fc3_w,
    const float* __restrict__ fc4_w, const float* __restrict__ fc4_b,
    const float* __restrict__ fc5_w, const float* __restrict__ fc5_b,
    float* __restrict__ out) {
    __shared__ __align__(16) float xs[2048];
    __shared__ float sred[8];

    // fc3: 2048x160000. 4096 chunks = 256 row-groups(8 rows) x 16 col-splits.
    const int NC4 = 40000, CHUNK = 2500, NCHUNK = 4096;
    for (int c = blockIdx.x; c < NCHUNK; c += GB) {
        int rg = c >> 4, cs = c & 15;
        int r0 = rg * 8;
        if (threadIdx.x < 8) sred[threadIdx.x] = 0.f;
        __syncthreads();
        const float4* x4 = (const float4*)g_c4 + cs * CHUNK;
        const float4* w4 = (const float4*)fc3_w + (size_t)r0 * NC4 + cs * CHUNK;
        float a[8];
#pragma unroll
        for (int k = 0; k < 8; k++) a[k] = 0.f;
        for (int i = threadIdx.x; i < CHUNK; i += 256) {
            float4 xv = x4[i];
#pragma unroll
            for (int k = 0; k < 8; k++) {
                float4 w = __ldcs(&w4[i + k * NC4]);
                a[k] += w.x * xv.x + w.y * xv.y + w.z * xv.z + w.w * xv.w;
            }
        }
#pragma unroll
        for (int k = 0; k < 8; k++) a[k] = warp_red(a[k]);
        if ((threadIdx.x & 31) == 0) {
#pragma unroll
            for (int k = 0; k < 8; k++) atomicAdd(&sred[k], a[k]);
        }
        __syncthreads();
        if (threadIdx.x < 8) atomicAdd(&g_f3[r0 + threadIdx.x], sred[threadIdx.x]);
        __syncthreads();
    }
    gsync(GB);

    // fc4: 2048x2048, warp per row
    {
        for (int i = threadIdx.x; i < 2048; i += 256) xs[i] = __ldcg(&g_f3[i]);
        __syncthreads();
        int gt = blockIdx.x * 256 + threadIdx.x;
        int warp = gt >> 5, lane = gt & 31, nwarp = (GB * 256) >> 5;
        const float4* xs4 = (const float4*)xs;
        for (int r = warp; r < 2048; r += nwarp) {
            const float4* w4 = (const float4*)(fc4_w + (size_t)r * 2048);
            float a = 0.f;
#pragma unroll 4
            for (int i = lane; i < 512; i += 32) {
                float4 w = __ldcs(&w4[i]);
                float4 xv = xs4[i];
                a += w.x * xv.x + w.y * xv.y + w.z * xv.z + w.w * xv.w;
            }
            a = warp_red(a);
            if (lane == 0) g_f4[r] = a + fc4_b[r];
        }
    }
    gsync(GB);

    // fc5: 48x2048 -> out
    {
        for (int i = threadIdx.x; i < 2048; i += 256) xs[i] = __ldcg(&g_f4[i]);
        __syncthreads();
        int gt = blockIdx.x * 256 + threadIdx.x;
        int warp = gt >> 5, lane = gt & 31;
        if (warp < 48) {
            const float4* w4 = (const float4*)(fc5_w + (size_t)warp * 2048);
            const float4* xs4 = (const float4*)xs;
            float a = 0.f;
            for (int i = lane; i < 512; i += 32) {
                float4 w = w4[i];
                float4 xv = xs4[i];
                a += w.x * xv.x + w.y * xv.y + w.z * xv.z + w.w * xv.w;
            }
            a = warp_red(a);
            if (lane == 0) out[warp] = a + fc5_b[warp];
        }
    }
}

// ---------------- launcher ---------------------------------------------------
extern "C" void kernel_launch(void* const* d_in, const int* in_sizes, int n_in,
                              void* d_out, int out_size) {
    const float* x     = (const float*)d_in[0];
    const void*  ei    = d_in[1];
    const float* W1    = (const float*)d_in[2];
    const float* b1    = (const float*)d_in[3];
    const float* W2    = (const float*)d_in[4];
    const float* b2    = (const float*)d_in[5];
    const float* fc1_w = (const float*)d_in[6];
    const float* fc1_b = (const float*)d_in[7];
    const float* fc2_w = (const float*)d_in[8];
    const float* fc2_b = (const float*)d_in[9];
    const float* c1_w  = (const float*)d_in[10];
    const float* c1_b  = (const float*)d_in[11];
    const float* c2_w  = (const float*)d_in[12];
    const float* c2_b  = (const float*)d_in[13];
    const float* c3_w  = (const float*)d_in[14];
    const float* c3_b  = (const float*)d_in[15];
    const float* c4_w  = (const float*)d_in[16];
    const float* c4_b  = (const float*)d_in[17];
    const float* fc3_w = (const float*)d_in[18];
    const float* fc3_b = (const float*)d_in[19];
    const float* fc4_w = (const float*)d_in[20];
    const float* fc4_b = (const float*)d_in[21];
    const float* fc5_w = (const float*)d_in[22];
    const float* fc5_b = (const float*)d_in[23];
    float* out = (float*)d_out;

    k_gcn<<<G1, 256>>>(x, ei, W1, b1, W2, fc1_b, fc3_b);
    k_fc<<<G2, 256>>>(b2, fc1_w, fc2_w, fc2_b, c2_b, c3_b, c4_b);
    k_conv<<<G3, 256>>>(c1_w, c1_b, c2_w, c2_b, c3_w, c3_b, c4_w, c4_b);
    kB<<<GB, 256>>>(fc3_w, fc4_w, fc4_b, fc5_w, fc5_b, out);
}